// round 15
// baseline (speedup 1.0000x reference)
#include <cuda_runtime.h>
#include <cuda_bf16.h>
#include <cstdint>

// x: [8,64,64,512] f32; w_theta [512,64]; w_phi [512,64]; w_g [512,256]; w_o [256,512]; gamma [1]
#define M_TOT   32768
#define C_IN    512
#define CK      64
#define CV      256
#define NPROJ   384
#define HW      4096
#define HWP     1024

// -------------------- scratch (device globals) --------------------
__device__ __nv_bfloat16 g_WcatT[(size_t)NPROJ * C_IN];   // [384][512]  W^T (theta|phi|g)
__device__ __nv_bfloat16 g_WoT[(size_t)C_IN * CV];        // [512][256]  w_o^T
__device__ __nv_bfloat16 g_Xbf[(size_t)M_TOT * C_IN];     // x in bf16
__device__ __nv_bfloat16 g_Y[(size_t)M_TOT * NPROJ];      // proj outputs
__device__ __nv_bfloat16 g_phiP[(size_t)8 * HWP * CK];    // pooled phi [b][p][ck]
__device__ __nv_bfloat16 g_vT[(size_t)8 * CV * HWP];      // pooled g, transposed [b][v][p]
__device__ __nv_bfloat16 g_O[(size_t)M_TOT * CV];         // attn output

// ---------------------------------------------------------------------------
__device__ __forceinline__ uint32_t smem_u32(const void* p) {
    uint32_t a;
    asm("{ .reg .u64 t; cvta.to.shared.u64 t, %1; cvt.u32.u64 %0, t; }" : "=r"(a) : "l"(p));
    return a;
}
__device__ __forceinline__ void mma16816(float* d, const unsigned* a, const unsigned* b) {
    asm volatile(
        "mma.sync.aligned.m16n8k16.row.col.f32.bf16.bf16.f32 "
        "{%0,%1,%2,%3}, {%4,%5,%6,%7}, {%8,%9}, {%0,%1,%2,%3};\n"
        : "+f"(d[0]), "+f"(d[1]), "+f"(d[2]), "+f"(d[3])
        : "r"(a[0]), "r"(a[1]), "r"(a[2]), "r"(a[3]), "r"(b[0]), "r"(b[1]));
}
__device__ __forceinline__ void ldsm4(unsigned r[4], uint32_t addr) {
    asm volatile("ldmatrix.sync.aligned.m8n8.x4.shared.b16 {%0,%1,%2,%3}, [%4];"
                 : "=r"(r[0]), "=r"(r[1]), "=r"(r[2]), "=r"(r[3]) : "r"(addr));
}
__device__ __forceinline__ void cp16(uint32_t d, const void* g) {
    asm volatile("cp.async.cg.shared.global [%0], [%1], 16;" :: "r"(d), "l"(g));
}
#define CP_COMMIT() asm volatile("cp.async.commit_group;" ::: "memory")
#define CP_WAIT1()  asm volatile("cp.async.wait_group 1;"  ::: "memory")
#define CP_WAIT2()  asm volatile("cp.async.wait_group 2;"  ::: "memory")
#define CP_WAIT0()  asm volatile("cp.async.wait_group 0;"  ::: "memory")
#define BAR_GRP(id) asm volatile("bar.sync %0, %1;" :: "r"(id), "r"(128) : "memory")

__device__ __forceinline__ unsigned packbf2(float x, float y) {
    __nv_bfloat162 h = __floats2bfloat162_rn(x, y);
    return *(unsigned*)&h;
}

// Coalesced 16-col bf16 store via quad shfl exchange (32B contiguous per quad).
__device__ __forceinline__ void store16(__nv_bfloat16* rowptr, int colbase,
                                        unsigned u0, unsigned u1, int t, int lane)
{
    int srcl = (lane & ~3) | ((2 * t) & 3);
    unsigned a  = __shfl_sync(0xffffffffu, u0, srcl);
    unsigned b  = __shfl_sync(0xffffffffu, u1, srcl);
    unsigned a2 = __shfl_sync(0xffffffffu, u0, srcl + 1);
    unsigned b2 = __shfl_sync(0xffffffffu, u1, srcl + 1);
    uint2 w;
    w.x = (t < 2) ? a : b;
    w.y = (t < 2) ? a2 : b2;
    *(uint2*)(rowptr + colbase + 4 * t) = w;
}

// ---------------------------------------------------------------------------
// GEMM tiles: [*][72] bf16 rows (144 B, odd multiple of 16 -> ldsm conflict-free)
// ---------------------------------------------------------------------------
#define ASTG 18432             // 128*144
#define BSTG 36864             // 256*144
#define GSMEM   (6 * ASTG)
#define WSMEM4  (4 * (ASTG + BSTG))   // 221184 (4-stage wide)

__device__ __forceinline__ uint32_t a_lane_off(int wm, int lane) {
    return (uint32_t)((wm * 64 + (lane & 15)) * 144 + ((lane >> 4) << 4));
}
__device__ __forceinline__ uint32_t b_lane_off(int wn, int lane) {
    return (uint32_t)((wn * 32 + (lane & 7) + ((lane & 16) ? 8 : 0)) * 144
                      + ((lane & 8) ? 16 : 0));
}
__device__ __forceinline__ void gemm_chunk64(uint32_t aBase, uint32_t bBase, float acc[4][4][4])
{
    #pragma unroll
    for (int k16 = 0; k16 < 4; k16++) {
        unsigned a[4][4], bb[2][4];
        #pragma unroll
        for (int mi = 0; mi < 4; mi++) ldsm4(a[mi], aBase + mi * 16 * 144 + k16 * 32);
        #pragma unroll
        for (int np = 0; np < 2; np++) ldsm4(bb[np], bBase + np * 16 * 144 + k16 * 32);
        #pragma unroll
        for (int mi = 0; mi < 4; mi++) {
            mma16816(acc[mi][0], a[mi], &bb[0][0]);
            mma16816(acc[mi][1], a[mi], &bb[0][2]);
            mma16816(acc[mi][2], a[mi], &bb[1][0]);
            mma16816(acc[mi][3], a[mi], &bb[1][2]);
        }
    }
}
__device__ __forceinline__ void issue_stage(uint32_t smA, uint32_t smB, uint32_t cpoff,
    const __nv_bfloat16* ga, const __nv_bfloat16* gb, int s)
{
    uint32_t da = smA + s * ASTG + cpoff;
    uint32_t db = smB + s * ASTG + cpoff;
    #pragma unroll
    for (int j = 0; j < 4; j++) {
        cp16(da + j * 16, ga + j * 8);
        cp16(db + j * 16, gb + j * 8);
    }
}
template<int NIT>
__device__ __forceinline__ void gemm_mainloop(
    uint32_t smA, uint32_t smB, uint32_t cpoff, uint32_t aoff, uint32_t boff,
    const __nv_bfloat16* Arow_g, const __nv_bfloat16* Brow_g, float acc[4][4][4])
{
    issue_stage(smA, smB, cpoff, Arow_g, Brow_g, 0);
    CP_COMMIT();
    issue_stage(smA, smB, cpoff, Arow_g + 64, Brow_g + 64, 1);
    CP_COMMIT();
    #pragma unroll
    for (int it = 0; it < NIT; it++) {
        CP_WAIT1();
        __syncthreads();
        int s = it % 3;
        gemm_chunk64(smA + s * ASTG + aoff, smB + s * ASTG + boff, acc);
        if (it + 2 < NIT)
            issue_stage(smA, smB, cpoff, Arow_g + (it + 2) * 64, Brow_g + (it + 2) * 64,
                        (it + 2) % 3);
        CP_COMMIT();
    }
}
// 4-stage wide (128x256, 512 thr) mainloop: 3 stages in flight, CP_WAIT2
// gives ~2 chunks of compute to cover the 577-cyc DRAM latency.
template<int NIT>
__device__ __forceinline__ void wide_mainloop4(
    uint32_t smA, uint32_t smB, uint32_t cpA, uint32_t cpB,
    uint32_t aoff, uint32_t boff,
    const __nv_bfloat16* Ag, const __nv_bfloat16* Bg, float acc[4][4][4])
{
    #pragma unroll
    for (int s = 0; s < 3; s++) {
        if (s < NIT) {
            uint32_t da = smA + s * ASTG + cpA;
            cp16(da, Ag + s * 64); cp16(da + 16, Ag + s * 64 + 8);
            uint32_t db = smB + s * BSTG + cpB;
            #pragma unroll
            for (int j = 0; j < 4; j++) cp16(db + j * 16, Bg + s * 64 + j * 8);
        }
        CP_COMMIT();
    }
    #pragma unroll
    for (int it = 0; it < NIT; it++) {
        CP_WAIT2();
        __syncthreads();
        int s = it & 3;
        gemm_chunk64(smA + s * ASTG + aoff, smB + s * BSTG + boff, acc);
        if (it + 3 < NIT) {
            int s2 = (it + 3) & 3;
            uint32_t da = smA + s2 * ASTG + cpA;
            cp16(da, Ag + (it + 3) * 64); cp16(da + 16, Ag + (it + 3) * 64 + 8);
            uint32_t db = smB + s2 * BSTG + cpB;
            #pragma unroll
            for (int j = 0; j < 4; j++) cp16(db + j * 16, Bg + (it + 3) * 64 + j * 8);
        }
        CP_COMMIT();
    }
}

// ===========================================================================
// K-1 xbf: x f32 -> bf16
// ===========================================================================
__global__ __launch_bounds__(256) void xbf_kernel(const float* __restrict__ x)
{
    size_t i = ((size_t)blockIdx.x * 256 + threadIdx.x) * 8;
    float4 a = *(const float4*)(x + i);
    float4 b = *(const float4*)(x + i + 4);
    uint4 o;
    o.x = packbf2(a.x, a.y); o.y = packbf2(a.z, a.w);
    o.z = packbf2(b.x, b.y); o.w = packbf2(b.z, b.w);
    *(uint4*)&g_Xbf[i] = o;
}

// ===========================================================================
// K0 prep: weights -> bf16 transposed
// ===========================================================================
__global__ __launch_bounds__(256) void prep_kernel(
    const float* __restrict__ wt, const float* __restrict__ wp,
    const float* __restrict__ wg, const float* __restrict__ wo)
{
    int idx = blockIdx.x * 256 + threadIdx.x;
    if (idx < NPROJ * C_IN) {
        int k = idx & 511, n = idx >> 9;
        float v = (n < 64)  ? wt[k * CK + n]
                : (n < 128) ? wp[k * CK + (n - 64)]
                            : wg[k * CV + (n - 128)];
        g_WcatT[idx] = __float2bfloat16(v);
    } else if (idx < NPROJ * C_IN + C_IN * CV) {
        int i2 = idx - NPROJ * C_IN;
        int k = i2 & 255, n = i2 >> 8;
        g_WoT[i2] = __float2bfloat16(wo[(size_t)k * C_IN + n]);
    }
}

// ===========================================================================
// K1 proj: Y[32768,384] = g_Xbf @ WcatT^T.  grid (3, 256), 256 thr
// ===========================================================================
__global__ __launch_bounds__(256, 2) void proj_kernel()
{
    extern __shared__ unsigned char sm[];
    const int m0 = blockIdx.y * 128, n0 = blockIdx.x * 128;
    const int tid = threadIdx.x, warp = tid >> 5, lane = tid & 31;
    const int wm = warp >> 2, wn = warp & 3, g = lane >> 2, t = lane & 3;

    uint32_t smA = smem_u32(sm), smB = smA + 3 * ASTG;
    uint32_t cpoff = (uint32_t)((tid >> 1) * 144 + (tid & 1) * 64);
    uint32_t aoff = a_lane_off(wm, lane), boff = b_lane_off(wn, lane);

    float acc[4][4][4];
    #pragma unroll
    for (int mi = 0; mi < 4; mi++)
        #pragma unroll
        for (int ni = 0; ni < 4; ni++)
            #pragma unroll
            for (int j = 0; j < 4; j++) acc[mi][ni][j] = 0.f;

    const __nv_bfloat16* Arow = g_Xbf   + (size_t)(m0 + (tid >> 1)) * C_IN + (tid & 1) * 32;
    const __nv_bfloat16* Brow = g_WcatT + (size_t)(n0 + (tid >> 1)) * C_IN + (tid & 1) * 32;
    gemm_mainloop<C_IN / 64>(smA, smB, cpoff, aoff, boff, Arow, Brow, acc);

    #pragma unroll
    for (int mi = 0; mi < 4; mi++)
        #pragma unroll
        for (int nip = 0; nip < 2; nip++) {
            int row = m0 + wm * 64 + mi * 16 + g;
            int colbase = n0 + wn * 32 + nip * 16;
            unsigned u0 = packbf2(acc[mi][2*nip][0],   acc[mi][2*nip][1]);
            unsigned u1 = packbf2(acc[mi][2*nip+1][0], acc[mi][2*nip+1][1]);
            store16(g_Y + (size_t)row * NPROJ, colbase, u0, u1, t, lane);
            unsigned v0 = packbf2(acc[mi][2*nip][2],   acc[mi][2*nip][3]);
            unsigned v1 = packbf2(acc[mi][2*nip+1][2], acc[mi][2*nip+1][3]);
            store16(g_Y + (size_t)(row + 8) * NPROJ, colbase, v0, v1, t, lane);
        }
}

// ===========================================================================
// K2a poolphi: phi -> g_phiP [b][p][ck]
// ===========================================================================
__global__ __launch_bounds__(256) void poolphi_kernel()
{
    int idx = blockIdx.x * 256 + threadIdx.x;
    int j = idx & 63, pp = (idx >> 6) & 1023, b = idx >> 16;
    int h2 = pp >> 5, w2 = pp & 31;
    size_t base = (size_t)b * HW;
    float m = -1e30f;
    #pragma unroll
    for (int dh = 0; dh < 2; dh++)
        #pragma unroll
        for (int dw = 0; dw < 2; dw++) {
            int p = (2 * h2 + dh) * 64 + 2 * w2 + dw;
            m = fmaxf(m, __bfloat162float(g_Y[(base + p) * NPROJ + 64 + j]));
        }
    g_phiP[idx] = __float2bfloat16(m);
}

// ===========================================================================
// K2b poolvT: g (Y cols 128..383) -> pooled + transposed g_vT [b][v][p]
// ===========================================================================
__global__ __launch_bounds__(256) void poolvT_kernel()
{
    __shared__ __nv_bfloat16 smT[32][72];
    const int b = blockIdx.z, v0 = blockIdx.y * 32, pp0 = blockIdx.x * 64;
    const int tid = threadIdx.x;
    {
        int pp_l = tid & 63, vg = tid >> 6;
        int pp = pp0 + pp_l, h2 = pp >> 5, w2 = pp & 31;
        const __nv_bfloat16* base =
            g_Y + (size_t)b * HW * NPROJ + 128 + v0 + vg * 8;
        int p00 = (2 * h2) * 64 + 2 * w2;
        uint4 u0 = *(const uint4*)(base + (size_t)p00 * NPROJ);
        uint4 u1 = *(const uint4*)(base + (size_t)(p00 + 1) * NPROJ);
        uint4 u2 = *(const uint4*)(base + (size_t)(p00 + 64) * NPROJ);
        uint4 u3 = *(const uint4*)(base + (size_t)(p00 + 65) * NPROJ);
        const __nv_bfloat162* a0 = (const __nv_bfloat162*)&u0;
        const __nv_bfloat162* a1 = (const __nv_bfloat162*)&u1;
        const __nv_bfloat162* a2 = (const __nv_bfloat162*)&u2;
        const __nv_bfloat162* a3 = (const __nv_bfloat162*)&u3;
        #pragma unroll
        for (int q = 0; q < 4; q++) {
            __nv_bfloat162 m = __hmax2(__hmax2(a0[q], a1[q]), __hmax2(a2[q], a3[q]));
            smT[vg * 8 + 2 * q][pp_l]     = __low2bfloat16(m);
            smT[vg * 8 + 2 * q + 1][pp_l] = __high2bfloat16(m);
        }
    }
    __syncthreads();
    {
        int v_l = tid & 31, ppc = tid >> 5;
        uint4 val = *(const uint4*)&smT[v_l][ppc * 8];
        *(uint4*)&g_vT[((size_t)b * CV + v0 + v_l) * HWP + pp0 + ppc * 8] = val;
    }
}

// ===========================================================================
// K3 fused attention: per CTA 64 queries x full KV=1024 (8 chunks of 128).
// Online softmax; O accum in regs; P chunk via smem; K/V cp.async rings.
// 512 thr / 16 warps; warp tile: S 16x32, O 16x64 (wm=warp>>2, wn=warp&3).
// Softmax reductions are scoped to the 4 warps sharing wm (threads
// [128*wm, 128*wm+128)) -> named barrier (1+wm), not CTA-wide syncs.
// Smem: Ps 64x272B @0 | Mrow @17408 | Srow @17664 | rmax @17920 | rsum @18944
//       Qs 64x144 @19968 | K ring 2x18432 @29184 | V ring 4x36864 @66048
// ===========================================================================
#define PS_OFF   0
#define MROW_OFF 17408
#define SROW_OFF 17664
#define RMAX_OFF 17920
#define RSUM_OFF 18944
#define QS_OFF   19968
#define KS_OFF   29184
#define VS_OFF   66048
#define ATTN_SMEM 213504

__device__ __forceinline__ void attn_issueK(uint32_t KsB, int tid,
                                            const __nv_bfloat16* Kg, int ch)
{
    int kr = tid >> 2, kq = (tid & 3) * 32;   // row 0..127, byte quarter
    uint32_t d = KsB + (uint32_t)(ch & 1) * ASTG + (uint32_t)(kr * 144 + kq);
    const __nv_bfloat16* s = Kg + (size_t)(ch * 128 + kr) * CK + (tid & 3) * 16;
    cp16(d, s); cp16(d + 16, s + 8);
}
__device__ __forceinline__ void attn_issueV(uint32_t VsB, int tid,
                                            const __nv_bfloat16* Vg, int hv)
{
    int vr = tid >> 1, vh = (tid & 1) * 64;   // row n 0..255, byte half
    uint32_t d = VsB + (uint32_t)(hv & 3) * BSTG + (uint32_t)(vr * 144 + vh);
    const __nv_bfloat16* s = Vg + (size_t)vr * HWP + hv * 64 + (tid & 1) * 32;
    #pragma unroll
    for (int j = 0; j < 4; j++) cp16(d + j * 16, s + j * 8);
}

__global__ __launch_bounds__(512, 1) void attn_fused_kernel()
{
    extern __shared__ unsigned char sm[];
    const uint32_t SB = smem_u32(sm);
    __nv_bfloat16* Ps = (__nv_bfloat16*)(sm + PS_OFF);
    float* Mrow   = (float*)(sm + MROW_OFF);
    float* Srow   = (float*)(sm + SROW_OFF);
    float* redmax = (float*)(sm + RMAX_OFF);   // [64][4]
    float* redsum = (float*)(sm + RSUM_OFF);   // [64][4]
    const uint32_t QsB = SB + QS_OFF, KsB = SB + KS_OFF, VsB = SB + VS_OFF;

    const int tid = threadIdx.x, warp = tid >> 5, lane = tid & 31;
    const int wm = warp >> 2, wn = warp & 3, g = lane >> 2, t = lane & 3;
    const int m0 = blockIdx.x * 64, b = blockIdx.y;
    const int row0 = wm * 16 + g, row1 = row0 + 8;
    const int barid = 1 + wm;   // named barrier for the 4 warps sharing wm

    if (tid < 64) { Mrow[tid] = -1e30f; Srow[tid] = 0.f; }

    // Q: 64 rows x 64 els -> Qs (stride 144).  uint4 = 8 els/thread = full tile.
    {
        int r = tid >> 3, c = (tid & 7) * 8;
        uint4 v0 = *(const uint4*)&g_Y[(size_t)(b * HW + m0 + r) * NPROJ + c];
        *(uint4*)(sm + QS_OFF + r * 144 + c * 2) = v0;
    }

    const __nv_bfloat16* Kg = g_phiP + (size_t)b * HWP * CK;
    const __nv_bfloat16* Vg = g_vT   + (size_t)b * CV * HWP;

    attn_issueK(KsB, tid, Kg, 0); attn_issueV(VsB, tid, Vg, 0); CP_COMMIT();
    attn_issueV(VsB, tid, Vg, 1); CP_COMMIT();

    __syncthreads();   // Qs + stats visible

    // cache Q fragments (1 m-frag x 4 k16)
    unsigned qa[4][4];
    #pragma unroll
    for (int kk = 0; kk < 4; kk++)
        ldsm4(qa[kk], QsB + (uint32_t)((wm * 16 + (lane & 15)) * 144
                                       + ((lane >> 4) << 4) + kk * 32));

    float oacc[8][4];
    #pragma unroll
    for (int nj = 0; nj < 8; nj++)
        #pragma unroll
        for (int j = 0; j < 4; j++) oacc[nj][j] = 0.f;

    const uint32_t klane = (uint32_t)((wn * 32 + (lane & 7) + ((lane & 16) ? 8 : 0)) * 144
                                      + ((lane & 8) ? 16 : 0));
    const uint32_t vlane = (uint32_t)((wn * 64 + (lane & 7) + ((lane & 16) ? 8 : 0)) * 144
                                      + ((lane & 8) ? 16 : 0));
    const uint32_t plane = (uint32_t)((wm * 16 + (lane & 15)) * 272 + ((lane >> 4) << 4));

    for (int ch = 0; ch < 8; ch++) {
        CP_WAIT0();
        __syncthreads();   // chunk's K,V staged; prev chunk's PV fully done (ring safety)
        if (ch + 1 < 8) { attn_issueK(KsB, tid, Kg, ch + 1); attn_issueV(VsB, tid, Vg, 2 * ch + 2); }
        CP_COMMIT();
        if (ch + 1 < 8) attn_issueV(VsB, tid, Vg, 2 * ch + 3);
        CP_COMMIT();

        // ---- S = Q @ K^T : warp 16m x 32n ----
        uint32_t kb = KsB + (uint32_t)(ch & 1) * ASTG + klane;
        float sacc[4][4];
        #pragma unroll
        for (int nj = 0; nj < 4; nj++)
            #pragma unroll
            for (int j = 0; j < 4; j++) sacc[nj][j] = 0.f;
        #pragma unroll
        for (int kk = 0; kk < 4; kk++) {
            unsigned b0[4], b1[4];
            ldsm4(b0, kb + kk * 32);
            ldsm4(b1, kb + 16 * 144 + kk * 32);
            mma16816(sacc[0], qa[kk], &b0[0]);
            mma16816(sacc[1], qa[kk], &b0[2]);
            mma16816(sacc[2], qa[kk], &b1[0]);
            mma16816(sacc[3], qa[kk], &b1[2]);
        }

        // ---- chunk row max (warp-local, then cross-warp within wm group) ----
        float lm0 = -1e30f, lm1 = -1e30f;
        #pragma unroll
        for (int nj = 0; nj < 4; nj++) {
            lm0 = fmaxf(lm0, fmaxf(sacc[nj][0], sacc[nj][1]));
            lm1 = fmaxf(lm1, fmaxf(sacc[nj][2], sacc[nj][3]));
        }
        lm0 = fmaxf(lm0, __shfl_xor_sync(0xffffffffu, lm0, 1));
        lm0 = fmaxf(lm0, __shfl_xor_sync(0xffffffffu, lm0, 2));
        lm1 = fmaxf(lm1, __shfl_xor_sync(0xffffffffu, lm1, 1));
        lm1 = fmaxf(lm1, __shfl_xor_sync(0xffffffffu, lm1, 2));
        if (t == 0) { redmax[row0 * 4 + wn] = lm0; redmax[row1 * 4 + wn] = lm1; }
        BAR_GRP(barid);

        float cm0 = fmaxf(fmaxf(redmax[row0 * 4], redmax[row0 * 4 + 1]),
                          fmaxf(redmax[row0 * 4 + 2], redmax[row0 * 4 + 3]));
        float cm1 = fmaxf(fmaxf(redmax[row1 * 4], redmax[row1 * 4 + 1]),
                          fmaxf(redmax[row1 * 4 + 2], redmax[row1 * 4 + 3]));
        float om0 = Mrow[row0], om1 = Mrow[row1];
        float nm0 = fmaxf(om0, cm0), nm1 = fmaxf(om1, cm1);
        float al0 = __expf(om0 - nm0), al1 = __expf(om1 - nm1);

        // exp + chunk sums + P write + O rescale
        float ls0 = 0.f, ls1 = 0.f;
        #pragma unroll
        for (int nj = 0; nj < 4; nj++) {
            float e0 = __expf(sacc[nj][0] - nm0);
            float e1 = __expf(sacc[nj][1] - nm0);
            float e2 = __expf(sacc[nj][2] - nm1);
            float e3 = __expf(sacc[nj][3] - nm1);
            ls0 += e0 + e1; ls1 += e2 + e3;
            int col = wn * 32 + nj * 8 + 2 * t;
            *(unsigned*)&Ps[row0 * 136 + col] = packbf2(e0, e1);
            *(unsigned*)&Ps[row1 * 136 + col] = packbf2(e2, e3);
        }
        ls0 += __shfl_xor_sync(0xffffffffu, ls0, 1);
        ls0 += __shfl_xor_sync(0xffffffffu, ls0, 2);
        ls1 += __shfl_xor_sync(0xffffffffu, ls1, 1);
        ls1 += __shfl_xor_sync(0xffffffffu, ls1, 2);
        if (t == 0) { redsum[row0 * 4 + wn] = ls0; redsum[row1 * 4 + wn] = ls1; }
        #pragma unroll
        for (int nj = 0; nj < 8; nj++) {
            oacc[nj][0] *= al0; oacc[nj][1] *= al0;
            oacc[nj][2] *= al1; oacc[nj][3] *= al1;
        }
        BAR_GRP(barid);   // Ps + redsum visible within wm group; old Mrow consumed

        if (wn == 0 && t == 0) {
            Srow[row0] = Srow[row0] * al0 +
                (redsum[row0 * 4] + redsum[row0 * 4 + 1] + redsum[row0 * 4 + 2] + redsum[row0 * 4 + 3]);
            Srow[row1] = Srow[row1] * al1 +
                (redsum[row1 * 4] + redsum[row1 * 4 + 1] + redsum[row1 * 4 + 2] + redsum[row1 * 4 + 3]);
            Mrow[row0] = nm0; Mrow[row1] = nm1;
        }

        // ---- O += P @ V : warp 16m x 64n, chunk k=128 in two 64-key halves ----
        #pragma unroll
        for (int h = 0; h < 2; h++) {
            uint32_t vb = VsB + (uint32_t)((2 * ch + h) & 3) * BSTG + vlane;
            uint32_t pb = SB + PS_OFF + plane + (uint32_t)h * 128;
            #pragma unroll
            for (int kk = 0; kk < 4; kk++) {
                unsigned pa[4];
                ldsm4(pa, pb + kk * 32);
                #pragma unroll
                for (int np = 0; np < 4; np++) {
                    unsigned vv[4];
                    ldsm4(vv, vb + np * 16 * 144 + kk * 32);
                    mma16816(oacc[2 * np],     pa, &vv[0]);
                    mma16816(oacc[2 * np + 1], pa, &vv[2]);
                }
            }
        }
    }

    __syncthreads();   // final Srow/Mrow visible
    float inv0 = 1.f / Srow[row0], inv1 = 1.f / Srow[row1];

    int grow = b * HW + m0 + row0;
    #pragma unroll
    for (int nip = 0; nip < 4; nip++) {
        int colbase = wn * 64 + nip * 16;
        unsigned u0 = packbf2(oacc[2*nip][0] * inv0,   oacc[2*nip][1] * inv0);
        unsigned u1 = packbf2(oacc[2*nip+1][0] * inv0, oacc[2*nip+1][1] * inv0);
        store16(g_O + (size_t)grow * CV, colbase, u0, u1, t, lane);
        unsigned v0 = packbf2(oacc[2*nip][2] * inv1,   oacc[2*nip][3] * inv1);
        unsigned v1 = packbf2(oacc[2*nip+1][2] * inv1, oacc[2*nip+1][3] * inv1);
        store16(g_O + (size_t)(grow + 8) * CV, colbase, v0, v1, t, lane);
    }
}

// ===========================================================================
// K5 out: out = x + gamma * (g_O @ w_o).  128x256 tile, 512 thr, 4-stage.
// ===========================================================================
__global__ __launch_bounds__(512, 1) void out_kernel(
    const float* __restrict__ x, const float* __restrict__ gamma,
    float* __restrict__ out)
{
    extern __shared__ unsigned char sm[];
    const int n0 = blockIdx.x * 256, m0 = blockIdx.y * 128;
    const int tid = threadIdx.x, warp = tid >> 5, lane = tid & 31;
    const int wm = warp >> 3, wn = warp & 7, g = lane >> 2, t = lane & 3;

    uint32_t smA = smem_u32(sm), smB = smA + 4 * ASTG;
    uint32_t cpA = (uint32_t)((tid >> 2) * 144 + (tid & 3) * 32);
    uint32_t cpB = (uint32_t)((tid >> 1) * 144 + (tid & 1) * 64);
    uint32_t aoff = a_lane_off(wm, lane), boff = b_lane_off(wn, lane);

    float acc[4][4][4];
    #pragma unroll
    for (int mi = 0; mi < 4; mi++)
        #pragma unroll
        for (int ni = 0; ni < 4; ni++)
            #pragma unroll
            for (int j = 0; j < 4; j++) acc[mi][ni][j] = 0.f;

    const __nv_bfloat16* Ag = g_O   + (size_t)(m0 + (tid >> 2)) * CV + (tid & 3) * 16;
    const __nv_bfloat16* Bg = g_WoT + (size_t)(n0 + (tid >> 1)) * CV + (tid & 1) * 32;
    wide_mainloop4<CV / 64>(smA, smB, cpA, cpB, aoff, boff, Ag, Bg, acc);

    const float gam = gamma[0];
    #pragma unroll
    for (int mi = 0; mi < 4; mi++)
        #pragma unroll
        for (int ni = 0; ni < 4; ni++) {
            int row = m0 + wm * 64 + mi * 16 + g;
            int col = n0 + wn * 32 + ni * 8 + 2 * t;
            {
                float2 xv = *(const float2*)&x[(size_t)row * C_IN + col];
                float2 ov = make_float2(xv.x + gam * acc[mi][ni][0],
                                        xv.y + gam * acc[mi][ni][1]);
                *(float2*)&out[(size_t)row * C_IN + col] = ov;
            }
            {
                float2 xv = *(const float2*)&x[(size_t)(row + 8) * C_IN + col];
                float2 ov = make_float2(xv.x + gam * acc[mi][ni][2],
                                        xv.y + gam * acc[mi][ni][3]);
                *(float2*)&out[(size_t)(row + 8) * C_IN + col] = ov;
            }
        }
}

// ===========================================================================
extern "C" void kernel_launch(void* const* d_in, const int* in_sizes, int n_in,
                              void* d_out, int out_size)
{
    const float* x       = (const float*)d_in[0];
    const float* w_theta = (const float*)d_in[1];
    const float* w_phi   = (const float*)d_in[2];
    const float* w_g     = (const float*)d_in[3];
    const float* w_o     = (const float*)d_in[4];
    const float* gamma   = (const float*)d_in[5];
    float* out = (float*)d_out;
    (void)in_sizes; (void)n_in; (void)out_size;

    cudaFuncSetAttribute(proj_kernel, cudaFuncAttributeMaxDynamicSharedMemorySize, GSMEM);
    cudaFuncSetAttribute(out_kernel,  cudaFuncAttributeMaxDynamicSharedMemorySize, WSMEM4);
    cudaFuncSetAttribute(attn_fused_kernel, cudaFuncAttributeMaxDynamicSharedMemorySize, ATTN_SMEM);

    // K0: weight transpose/convert + x -> bf16
    {
        int total = NPROJ * C_IN + C_IN * CV;
        prep_kernel<<<(total + 255) / 256, 256>>>(w_theta, w_phi, w_g, w_o);
    }
    xbf_kernel<<<(M_TOT * C_IN / 8) / 256, 256>>>(x);
    // K1: projections
    proj_kernel<<<dim3(NPROJ / 128, M_TOT / 128), 256, GSMEM>>>();
    // K2: pooling
    poolphi_kernel<<<(8 * HWP * CK) / 256, 256>>>();
    poolvT_kernel<<<dim3(HWP / 64, CV / 32, 8), 256>>>();
    // K3: fused attention (S + softmax + PV)
    attn_fused_kernel<<<dim3(HW / 64, 8), 512, ATTN_SMEM>>>();
    // K5: output projection + residual (4-stage)
    out_kernel<<<dim3(C_IN / 256, M_TOT / 128), 512, WSMEM4>>>(x, gamma, out);
}

// round 16
// speedup vs baseline: 1.0494x; 1.0494x over previous
#include <cuda_runtime.h>
#include <cuda_bf16.h>
#include <cstdint>

// x: [8,64,64,512] f32; w_theta [512,64]; w_phi [512,64]; w_g [512,256]; w_o [256,512]; gamma [1]
#define M_TOT   32768
#define C_IN    512
#define CK      64
#define CV      256
#define NPROJ   384
#define HW      4096
#define HWP     1024

// -------------------- scratch (device globals) --------------------
__device__ __nv_bfloat16 g_WcatT[(size_t)NPROJ * C_IN];   // [384][512]  W^T (theta|phi|g)
__device__ __nv_bfloat16 g_WoT[(size_t)C_IN * CV];        // [512][256]  w_o^T
__device__ __nv_bfloat16 g_Xbf[(size_t)M_TOT * C_IN];     // x in bf16
__device__ __nv_bfloat16 g_Y[(size_t)M_TOT * NPROJ];      // proj outputs
__device__ __nv_bfloat16 g_phiP[(size_t)8 * HWP * CK];    // pooled phi [b][p][ck]
__device__ __nv_bfloat16 g_vT[(size_t)8 * CV * HWP];      // pooled g, transposed [b][v][p]
__device__ __nv_bfloat16 g_P[(size_t)8 * HW * HWP];       // softmax probs
__device__ __nv_bfloat16 g_O[(size_t)M_TOT * CV];         // attn output

// ---------------------------------------------------------------------------
__device__ __forceinline__ uint32_t smem_u32(const void* p) {
    uint32_t a;
    asm("{ .reg .u64 t; cvta.to.shared.u64 t, %1; cvt.u32.u64 %0, t; }" : "=r"(a) : "l"(p));
    return a;
}
__device__ __forceinline__ void mma16816(float* d, const unsigned* a, const unsigned* b) {
    asm volatile(
        "mma.sync.aligned.m16n8k16.row.col.f32.bf16.bf16.f32 "
        "{%0,%1,%2,%3}, {%4,%5,%6,%7}, {%8,%9}, {%0,%1,%2,%3};\n"
        : "+f"(d[0]), "+f"(d[1]), "+f"(d[2]), "+f"(d[3])
        : "r"(a[0]), "r"(a[1]), "r"(a[2]), "r"(a[3]), "r"(b[0]), "r"(b[1]));
}
__device__ __forceinline__ void ldsm4(unsigned r[4], uint32_t addr) {
    asm volatile("ldmatrix.sync.aligned.m8n8.x4.shared.b16 {%0,%1,%2,%3}, [%4];"
                 : "=r"(r[0]), "=r"(r[1]), "=r"(r[2]), "=r"(r[3]) : "r"(addr));
}
__device__ __forceinline__ void cp16(uint32_t d, const void* g) {
    asm volatile("cp.async.cg.shared.global [%0], [%1], 16;" :: "r"(d), "l"(g));
}
#define CP_COMMIT() asm volatile("cp.async.commit_group;" ::: "memory")
#define CP_WAIT1()  asm volatile("cp.async.wait_group 1;"  ::: "memory")

__device__ __forceinline__ unsigned packbf2(float x, float y) {
    __nv_bfloat162 h = __floats2bfloat162_rn(x, y);
    return *(unsigned*)&h;
}

// Coalesced 16-col bf16 store via quad shfl exchange (32B contiguous per quad).
__device__ __forceinline__ void store16(__nv_bfloat16* rowptr, int colbase,
                                        unsigned u0, unsigned u1, int t, int lane)
{
    int srcl = (lane & ~3) | ((2 * t) & 3);
    unsigned a  = __shfl_sync(0xffffffffu, u0, srcl);
    unsigned b  = __shfl_sync(0xffffffffu, u1, srcl);
    unsigned a2 = __shfl_sync(0xffffffffu, u0, srcl + 1);
    unsigned b2 = __shfl_sync(0xffffffffu, u1, srcl + 1);
    uint2 w;
    w.x = (t < 2) ? a : b;
    w.y = (t < 2) ? a2 : b2;
    *(uint2*)(rowptr + colbase + 4 * t) = w;
}

// ---------------------------------------------------------------------------
// GEMM tiles: [*][72] bf16 rows (144 B, odd multiple of 16 -> ldsm conflict-free)
// ---------------------------------------------------------------------------
#define ASTG 18432             // 128*144
#define BSTG 36864             // 256*144
#define GSMEM   (6 * ASTG)
#define WSMEM   (3 * ASTG + 3 * BSTG)   // 165888

__device__ __forceinline__ uint32_t a_lane_off(int wm, int lane) {
    return (uint32_t)((wm * 64 + (lane & 15)) * 144 + ((lane >> 4) << 4));
}
__device__ __forceinline__ uint32_t b_lane_off(int wn, int lane) {
    return (uint32_t)((wn * 32 + (lane & 7) + ((lane & 16) ? 8 : 0)) * 144
                      + ((lane & 8) ? 16 : 0));
}
__device__ __forceinline__ void gemm_chunk64(uint32_t aBase, uint32_t bBase, float acc[4][4][4])
{
    #pragma unroll
    for (int k16 = 0; k16 < 4; k16++) {
        unsigned a[4][4], bb[2][4];
        #pragma unroll
        for (int mi = 0; mi < 4; mi++) ldsm4(a[mi], aBase + mi * 16 * 144 + k16 * 32);
        #pragma unroll
        for (int np = 0; np < 2; np++) ldsm4(bb[np], bBase + np * 16 * 144 + k16 * 32);
        #pragma unroll
        for (int mi = 0; mi < 4; mi++) {
            mma16816(acc[mi][0], a[mi], &bb[0][0]);
            mma16816(acc[mi][1], a[mi], &bb[0][2]);
            mma16816(acc[mi][2], a[mi], &bb[1][0]);
            mma16816(acc[mi][3], a[mi], &bb[1][2]);
        }
    }
}
__device__ __forceinline__ void issue_stage(uint32_t smA, uint32_t smB, uint32_t cpoff,
    const __nv_bfloat16* ga, const __nv_bfloat16* gb, int s)
{
    uint32_t da = smA + s * ASTG + cpoff;
    uint32_t db = smB + s * ASTG + cpoff;
    #pragma unroll
    for (int j = 0; j < 4; j++) {
        cp16(da + j * 16, ga + j * 8);
        cp16(db + j * 16, gb + j * 8);
    }
}
template<int NIT>
__device__ __forceinline__ void gemm_mainloop(
    uint32_t smA, uint32_t smB, uint32_t cpoff, uint32_t aoff, uint32_t boff,
    const __nv_bfloat16* Arow_g, const __nv_bfloat16* Brow_g, float acc[4][4][4])
{
    issue_stage(smA, smB, cpoff, Arow_g, Brow_g, 0);
    CP_COMMIT();
    issue_stage(smA, smB, cpoff, Arow_g + 64, Brow_g + 64, 1);
    CP_COMMIT();
    #pragma unroll
    for (int it = 0; it < NIT; it++) {
        CP_WAIT1();
        __syncthreads();
        int s = it % 3;
        gemm_chunk64(smA + s * ASTG + aoff, smB + s * ASTG + boff, acc);
        if (it + 2 < NIT)
            issue_stage(smA, smB, cpoff, Arow_g + (it + 2) * 64, Brow_g + (it + 2) * 64,
                        (it + 2) % 3);
        CP_COMMIT();
    }
}
template<int NIT>
__device__ __forceinline__ void wide_mainloop(
    uint32_t smA, uint32_t smB, uint32_t cpA, uint32_t cpB,
    uint32_t aoff, uint32_t boff,
    const __nv_bfloat16* Ag, const __nv_bfloat16* Bg, float acc[4][4][4])
{
    #pragma unroll
    for (int s = 0; s < 2; s++) {
        uint32_t da = smA + s * ASTG + cpA;
        cp16(da, Ag + s * 64); cp16(da + 16, Ag + s * 64 + 8);
        uint32_t db = smB + s * BSTG + cpB;
        #pragma unroll
        for (int j = 0; j < 4; j++) cp16(db + j * 16, Bg + s * 64 + j * 8);
        CP_COMMIT();
    }
    #pragma unroll
    for (int it = 0; it < NIT; it++) {
        CP_WAIT1();
        __syncthreads();
        int s = it % 3;
        gemm_chunk64(smA + s * ASTG + aoff, smB + s * BSTG + boff, acc);
        if (it + 2 < NIT) {
            int s2 = (it + 2) % 3;
            uint32_t da = smA + s2 * ASTG + cpA;
            cp16(da, Ag + (it + 2) * 64); cp16(da + 16, Ag + (it + 2) * 64 + 8);
            uint32_t db = smB + s2 * BSTG + cpB;
            #pragma unroll
            for (int j = 0; j < 4; j++) cp16(db + j * 16, Bg + (it + 2) * 64 + j * 8);
        }
        CP_COMMIT();
    }
}

// ===========================================================================
// K0 prepxbf: (merged) x f32 -> bf16  AND  weights -> bf16 transposed.
// blocks [0, 8192): xbf; blocks [8192, 9472): weight prep.
// ===========================================================================
#define XBF_BLOCKS  8192      // (M_TOT*C_IN/8)/256
#define PREP_BLOCKS 1280      // ceil((NPROJ*C_IN + C_IN*CV)/256)

__global__ __launch_bounds__(256) void prepxbf_kernel(
    const float* __restrict__ x,
    const float* __restrict__ wt, const float* __restrict__ wp,
    const float* __restrict__ wg, const float* __restrict__ wo)
{
    if (blockIdx.x < XBF_BLOCKS) {
        size_t i = ((size_t)blockIdx.x * 256 + threadIdx.x) * 8;
        float4 a = *(const float4*)(x + i);
        float4 b = *(const float4*)(x + i + 4);
        uint4 o;
        o.x = packbf2(a.x, a.y); o.y = packbf2(a.z, a.w);
        o.z = packbf2(b.x, b.y); o.w = packbf2(b.z, b.w);
        *(uint4*)&g_Xbf[i] = o;
    } else {
        int idx = (blockIdx.x - XBF_BLOCKS) * 256 + threadIdx.x;
        if (idx < NPROJ * C_IN) {
            int k = idx & 511, n = idx >> 9;
            float v = (n < 64)  ? wt[k * CK + n]
                    : (n < 128) ? wp[k * CK + (n - 64)]
                                : wg[k * CV + (n - 128)];
            g_WcatT[idx] = __float2bfloat16(v);
        } else if (idx < NPROJ * C_IN + C_IN * CV) {
            int i2 = idx - NPROJ * C_IN;
            int k = i2 & 255, n = i2 >> 8;
            g_WoT[i2] = __float2bfloat16(wo[(size_t)k * C_IN + n]);
        }
    }
}

// ===========================================================================
// K1 proj: Y[32768,384] = g_Xbf @ WcatT^T.  grid (3, 256), 256 thr
// ===========================================================================
__global__ __launch_bounds__(256, 2) void proj_kernel()
{
    extern __shared__ unsigned char sm[];
    const int m0 = blockIdx.y * 128, n0 = blockIdx.x * 128;
    const int tid = threadIdx.x, warp = tid >> 5, lane = tid & 31;
    const int wm = warp >> 2, wn = warp & 3, g = lane >> 2, t = lane & 3;

    uint32_t smA = smem_u32(sm), smB = smA + 3 * ASTG;
    uint32_t cpoff = (uint32_t)((tid >> 1) * 144 + (tid & 1) * 64);
    uint32_t aoff = a_lane_off(wm, lane), boff = b_lane_off(wn, lane);

    float acc[4][4][4];
    #pragma unroll
    for (int mi = 0; mi < 4; mi++)
        #pragma unroll
        for (int ni = 0; ni < 4; ni++)
            #pragma unroll
            for (int j = 0; j < 4; j++) acc[mi][ni][j] = 0.f;

    const __nv_bfloat16* Arow = g_Xbf   + (size_t)(m0 + (tid >> 1)) * C_IN + (tid & 1) * 32;
    const __nv_bfloat16* Brow = g_WcatT + (size_t)(n0 + (tid >> 1)) * C_IN + (tid & 1) * 32;
    gemm_mainloop<C_IN / 64>(smA, smB, cpoff, aoff, boff, Arow, Brow, acc);

    #pragma unroll
    for (int mi = 0; mi < 4; mi++)
        #pragma unroll
        for (int nip = 0; nip < 2; nip++) {
            int row = m0 + wm * 64 + mi * 16 + g;
            int colbase = n0 + wn * 32 + nip * 16;
            unsigned u0 = packbf2(acc[mi][2*nip][0],   acc[mi][2*nip][1]);
            unsigned u1 = packbf2(acc[mi][2*nip+1][0], acc[mi][2*nip+1][1]);
            store16(g_Y + (size_t)row * NPROJ, colbase, u0, u1, t, lane);
            unsigned v0 = packbf2(acc[mi][2*nip][2],   acc[mi][2*nip][3]);
            unsigned v1 = packbf2(acc[mi][2*nip+1][2], acc[mi][2*nip+1][3]);
            store16(g_Y + (size_t)(row + 8) * NPROJ, colbase, v0, v1, t, lane);
        }
}

// ===========================================================================
// K2 pool (merged): blocks [0,2048) = poolphi; blocks [2048,3072) = poolvT.
// ===========================================================================
#define POOLPHI_BLOCKS 2048   // 8*HWP*CK / 256
#define POOLVT_BLOCKS  1024   // 16 * 8 * 8

__global__ __launch_bounds__(256) void pool_kernel()
{
    __shared__ __nv_bfloat16 smT[32][72];
    const int tid = threadIdx.x;

    if (blockIdx.x < POOLPHI_BLOCKS) {
        int idx = blockIdx.x * 256 + tid;
        int j = idx & 63, pp = (idx >> 6) & 1023, b = idx >> 16;
        int h2 = pp >> 5, w2 = pp & 31;
        size_t base = (size_t)b * HW;
        float m = -1e30f;
        #pragma unroll
        for (int dh = 0; dh < 2; dh++)
            #pragma unroll
            for (int dw = 0; dw < 2; dw++) {
                int p = (2 * h2 + dh) * 64 + 2 * w2 + dw;
                m = fmaxf(m, __bfloat162float(g_Y[(base + p) * NPROJ + 64 + j]));
            }
        g_phiP[idx] = __float2bfloat16(m);
        return;
    }

    // poolvT: bid -> (pp0, v0, b) as in round-11 grid (16, 8, 8)
    int bid = blockIdx.x - POOLPHI_BLOCKS;
    const int pp0 = (bid & 15) * 64;
    const int v0  = ((bid >> 4) & 7) * 32;
    const int b   = bid >> 7;
    {
        int pp_l = tid & 63, vg = tid >> 6;
        int pp = pp0 + pp_l, h2 = pp >> 5, w2 = pp & 31;
        const __nv_bfloat16* base =
            g_Y + (size_t)b * HW * NPROJ + 128 + v0 + vg * 8;
        int p00 = (2 * h2) * 64 + 2 * w2;
        uint4 u0 = *(const uint4*)(base + (size_t)p00 * NPROJ);
        uint4 u1 = *(const uint4*)(base + (size_t)(p00 + 1) * NPROJ);
        uint4 u2 = *(const uint4*)(base + (size_t)(p00 + 64) * NPROJ);
        uint4 u3 = *(const uint4*)(base + (size_t)(p00 + 65) * NPROJ);
        const __nv_bfloat162* a0 = (const __nv_bfloat162*)&u0;
        const __nv_bfloat162* a1 = (const __nv_bfloat162*)&u1;
        const __nv_bfloat162* a2 = (const __nv_bfloat162*)&u2;
        const __nv_bfloat162* a3 = (const __nv_bfloat162*)&u3;
        #pragma unroll
        for (int q = 0; q < 4; q++) {
            __nv_bfloat162 m = __hmax2(__hmax2(a0[q], a1[q]), __hmax2(a2[q], a3[q]));
            smT[vg * 8 + 2 * q][pp_l]     = __low2bfloat16(m);
            smT[vg * 8 + 2 * q + 1][pp_l] = __high2bfloat16(m);
        }
    }
    __syncthreads();
    {
        int v_l = tid & 31, ppc = tid >> 5;
        uint4 val = *(const uint4*)&smT[v_l][ppc * 8];
        *(uint4*)&g_vT[((size_t)b * CV + v0 + v_l) * HWP + pp0 + ppc * 8] = val;
    }
}

// ===========================================================================
// K3: S = Q @ phi^T -> softmax -> P (register-resident S), M-tile 16.
// ===========================================================================
#define S_SMEM (2816 + 3 * ASTG)   // 58112

__global__ __launch_bounds__(256, 2) void s_softmax_kernel()
{
    extern __shared__ unsigned char sm[];
    __nv_bfloat16* Qs = (__nv_bfloat16*)(sm);
    float*        red = (float*)(sm + 2304);
    const uint32_t KsB = smem_u32(sm) + 2816;

    const int tid = threadIdx.x, warp = tid >> 5, lane = tid & 31;
    const int g = lane >> 2, t = lane & 3;
    const int m0 = blockIdx.x * 16, b = blockIdx.y;

    if (tid < 128) {
        int r = tid >> 3, c0 = (tid & 7) * 8;
        const uint2* src = (const uint2*)&g_Y[(size_t)(b * HW + m0 + r) * NPROJ + c0];
        uint2* dst = (uint2*)&Qs[r * 72 + c0];
        dst[0] = src[0]; dst[1] = src[1];
    }

    const uint32_t kcp = KsB + (uint32_t)((tid >> 1) * 144 + (tid & 1) * 64);
    const __nv_bfloat16* Ksrc =
        g_phiP + ((size_t)b * HWP + (tid >> 1)) * CK + (tid & 1) * 32;
    #pragma unroll
    for (int j = 0; j < 4; j++) cp16(kcp + j * 16, Ksrc + j * 8);
    CP_COMMIT();
    #pragma unroll
    for (int j = 0; j < 4; j++) cp16(kcp + ASTG + j * 16, Ksrc + 128 * CK + j * 8);
    CP_COMMIT();

    __syncthreads();

    unsigned qa[4][4];
    #pragma unroll
    for (int kk = 0; kk < 4; kk++) {
        const __nv_bfloat16* p0 = Qs + g * 72 + kk * 16 + 2 * t;
        qa[kk][0] = *(const unsigned*)p0;
        qa[kk][1] = *(const unsigned*)(p0 + 8 * 72);
        qa[kk][2] = *(const unsigned*)(p0 + 8);
        qa[kk][3] = *(const unsigned*)(p0 + 8 * 72 + 8);
    }

    const uint32_t kslane = (uint32_t)((warp * 16 + (lane & 7)) * 144 + (lane >> 3) * 16);

    float sacc[2][8][4];
    #pragma unroll
    for (int ni = 0; ni < 2; ni++)
        #pragma unroll
        for (int ch = 0; ch < 8; ch++)
            #pragma unroll
            for (int j = 0; j < 4; j++) sacc[ni][ch][j] = 0.f;

    #pragma unroll
    for (int ch = 0; ch < 8; ch++) {
        CP_WAIT1();
        __syncthreads();
        uint32_t kbase = KsB + (uint32_t)(ch % 3) * ASTG + kslane;
        #pragma unroll
        for (int ni = 0; ni < 2; ni++) {
            unsigned b01[4], b23[4];
            ldsm4(b01, kbase + (uint32_t)ni * 8 * 144);
            ldsm4(b23, kbase + (uint32_t)ni * 8 * 144 + 64);
            mma16816(sacc[ni][ch], qa[0], &b01[0]);
            mma16816(sacc[ni][ch], qa[1], &b01[2]);
            mma16816(sacc[ni][ch], qa[2], &b23[0]);
            mma16816(sacc[ni][ch], qa[3], &b23[2]);
        }
        if (ch + 2 < 8) {
            const __nv_bfloat16* src = Ksrc + (size_t)(ch + 2) * 128 * CK;
            uint32_t dst = KsB + (uint32_t)((ch + 2) % 3) * ASTG +
                           (uint32_t)((tid >> 1) * 144 + (tid & 1) * 64);
            #pragma unroll
            for (int j = 0; j < 4; j++) cp16(dst + j * 16, src + j * 8);
        }
        CP_COMMIT();
    }

    // register softmax
    float mx0 = -1e30f, mx1 = -1e30f;
    #pragma unroll
    for (int ni = 0; ni < 2; ni++)
        #pragma unroll
        for (int ch = 0; ch < 8; ch++) {
            mx0 = fmaxf(mx0, fmaxf(sacc[ni][ch][0], sacc[ni][ch][1]));
            mx1 = fmaxf(mx1, fmaxf(sacc[ni][ch][2], sacc[ni][ch][3]));
        }
    mx0 = fmaxf(mx0, __shfl_xor_sync(0xffffffffu, mx0, 1));
    mx0 = fmaxf(mx0, __shfl_xor_sync(0xffffffffu, mx0, 2));
    mx1 = fmaxf(mx1, __shfl_xor_sync(0xffffffffu, mx1, 1));
    mx1 = fmaxf(mx1, __shfl_xor_sync(0xffffffffu, mx1, 2));
    if (t == 0) { red[g * 8 + warp] = mx0; red[(g + 8) * 8 + warp] = mx1; }
    __syncthreads();
    float M0 = -1e30f, M1 = -1e30f;
    #pragma unroll
    for (int w = 0; w < 8; w++) {
        M0 = fmaxf(M0, red[g * 8 + w]);
        M1 = fmaxf(M1, red[(g + 8) * 8 + w]);
    }
    __syncthreads();

    float s0 = 0.f, s1 = 0.f;
    #pragma unroll
    for (int ni = 0; ni < 2; ni++)
        #pragma unroll
        for (int ch = 0; ch < 8; ch++) {
            float e0 = __expf(sacc[ni][ch][0] - M0);
            float e1 = __expf(sacc[ni][ch][1] - M0);
            float e2 = __expf(sacc[ni][ch][2] - M1);
            float e3 = __expf(sacc[ni][ch][3] - M1);
            sacc[ni][ch][0] = e0; sacc[ni][ch][1] = e1;
            sacc[ni][ch][2] = e2; sacc[ni][ch][3] = e3;
            s0 += e0 + e1; s1 += e2 + e3;
        }
    s0 += __shfl_xor_sync(0xffffffffu, s0, 1);
    s0 += __shfl_xor_sync(0xffffffffu, s0, 2);
    s1 += __shfl_xor_sync(0xffffffffu, s1, 1);
    s1 += __shfl_xor_sync(0xffffffffu, s1, 2);
    if (t == 0) { red[g * 8 + warp] = s0; red[(g + 8) * 8 + warp] = s1; }
    __syncthreads();
    float S0 = 0.f, S1 = 0.f;
    #pragma unroll
    for (int w = 0; w < 8; w++) {
        S0 += red[g * 8 + w];
        S1 += red[(g + 8) * 8 + w];
    }
    float inv0 = 1.f / S0, inv1 = 1.f / S1;

    __nv_bfloat16* P0 = g_P + (size_t)(b * HW + m0 + g) * HWP;
    __nv_bfloat16* P1 = g_P + (size_t)(b * HW + m0 + g + 8) * HWP;
    #pragma unroll
    for (int ch = 0; ch < 8; ch++) {
        int colbase = ch * 128 + warp * 16;
        unsigned u0 = packbf2(sacc[0][ch][0] * inv0, sacc[0][ch][1] * inv0);
        unsigned u1 = packbf2(sacc[1][ch][0] * inv0, sacc[1][ch][1] * inv0);
        store16(P0, colbase, u0, u1, t, lane);
        unsigned v0 = packbf2(sacc[0][ch][2] * inv1, sacc[0][ch][3] * inv1);
        unsigned v1 = packbf2(sacc[1][ch][2] * inv1, sacc[1][ch][3] * inv1);
        store16(P1, colbase, v0, v1, t, lane);
    }
}

// ===========================================================================
// K4 PV: O[b][4096,256] = P[b] @ V[b]^T.  128x256 tile, 512 thr, grid (32, 8)
// ===========================================================================
__global__ __launch_bounds__(512, 1) void pv_kernel()
{
    extern __shared__ unsigned char sm[];
    const int b = blockIdx.y, m0 = blockIdx.x * 128;
    const int tid = threadIdx.x, warp = tid >> 5, lane = tid & 31;
    const int wm = warp >> 3, wn = warp & 7, g = lane >> 2, t = lane & 3;

    uint32_t smA = smem_u32(sm), smB = smA + 3 * ASTG;
    uint32_t cpA = (uint32_t)((tid >> 2) * 144 + (tid & 3) * 32);
    uint32_t cpB = (uint32_t)((tid >> 1) * 144 + (tid & 1) * 64);
    uint32_t aoff = a_lane_off(wm, lane), boff = b_lane_off(wn, lane);

    float acc[4][4][4];
    #pragma unroll
    for (int mi = 0; mi < 4; mi++)
        #pragma unroll
        for (int ni = 0; ni < 4; ni++)
            #pragma unroll
            for (int j = 0; j < 4; j++) acc[mi][ni][j] = 0.f;

    const __nv_bfloat16* Ag =
        g_P  + (size_t)b * HW * HWP + (size_t)(m0 + (tid >> 2)) * HWP + (tid & 3) * 16;
    const __nv_bfloat16* Bg =
        g_vT + (size_t)b * CV * HWP + (size_t)(tid >> 1) * HWP + (tid & 1) * 32;
    wide_mainloop<HWP / 64>(smA, smB, cpA, cpB, aoff, boff, Ag, Bg, acc);

    #pragma unroll
    for (int mi = 0; mi < 4; mi++)
        #pragma unroll
        for (int nip = 0; nip < 2; nip++) {
            int row = b * HW + m0 + wm * 64 + mi * 16 + g;
            int colbase = wn * 32 + nip * 16;
            unsigned u0 = packbf2(acc[mi][2*nip][0],   acc[mi][2*nip][1]);
            unsigned u1 = packbf2(acc[mi][2*nip+1][0], acc[mi][2*nip+1][1]);
            store16(g_O + (size_t)row * CV, colbase, u0, u1, t, lane);
            unsigned v0 = packbf2(acc[mi][2*nip][2],   acc[mi][2*nip][3]);
            unsigned v1 = packbf2(acc[mi][2*nip+1][2], acc[mi][2*nip+1][3]);
            store16(g_O + (size_t)(row + 8) * CV, colbase, v0, v1, t, lane);
        }
}

// ===========================================================================
// K5 out: out = x + gamma * (g_O @ w_o).  128x256 tile, 512 thr, grid (2, 256)
// ===========================================================================
__global__ __launch_bounds__(512, 1) void out_kernel(
    const float* __restrict__ x, const float* __restrict__ gamma,
    float* __restrict__ out)
{
    extern __shared__ unsigned char sm[];
    const int n0 = blockIdx.x * 256, m0 = blockIdx.y * 128;
    const int tid = threadIdx.x, warp = tid >> 5, lane = tid & 31;
    const int wm = warp >> 3, wn = warp & 7, g = lane >> 2, t = lane & 3;

    uint32_t smA = smem_u32(sm), smB = smA + 3 * ASTG;
    uint32_t cpA = (uint32_t)((tid >> 2) * 144 + (tid & 3) * 32);
    uint32_t cpB = (uint32_t)((tid >> 1) * 144 + (tid & 1) * 64);
    uint32_t aoff = a_lane_off(wm, lane), boff = b_lane_off(wn, lane);

    float acc[4][4][4];
    #pragma unroll
    for (int mi = 0; mi < 4; mi++)
        #pragma unroll
        for (int ni = 0; ni < 4; ni++)
            #pragma unroll
            for (int j = 0; j < 4; j++) acc[mi][ni][j] = 0.f;

    const __nv_bfloat16* Ag = g_O   + (size_t)(m0 + (tid >> 2)) * CV + (tid & 3) * 16;
    const __nv_bfloat16* Bg = g_WoT + (size_t)(n0 + (tid >> 1)) * CV + (tid & 1) * 32;
    wide_mainloop<CV / 64>(smA, smB, cpA, cpB, aoff, boff, Ag, Bg, acc);

    const float gam = gamma[0];
    #pragma unroll
    for (int mi = 0; mi < 4; mi++)
        #pragma unroll
        for (int ni = 0; ni < 4; ni++) {
            int row = m0 + wm * 64 + mi * 16 + g;
            int col = n0 + wn * 32 + ni * 8 + 2 * t;
            {
                float2 xv = *(const float2*)&x[(size_t)row * C_IN + col];
                float2 ov = make_float2(xv.x + gam * acc[mi][ni][0],
                                        xv.y + gam * acc[mi][ni][1]);
                *(float2*)&out[(size_t)row * C_IN + col] = ov;
            }
            {
                float2 xv = *(const float2*)&x[(size_t)(row + 8) * C_IN + col];
                float2 ov = make_float2(xv.x + gam * acc[mi][ni][2],
                                        xv.y + gam * acc[mi][ni][3]);
                *(float2*)&out[(size_t)(row + 8) * C_IN + col] = ov;
            }
        }
}

// ===========================================================================
extern "C" void kernel_launch(void* const* d_in, const int* in_sizes, int n_in,
                              void* d_out, int out_size)
{
    const float* x       = (const float*)d_in[0];
    const float* w_theta = (const float*)d_in[1];
    const float* w_phi   = (const float*)d_in[2];
    const float* w_g     = (const float*)d_in[3];
    const float* w_o     = (const float*)d_in[4];
    const float* gamma   = (const float*)d_in[5];
    float* out = (float*)d_out;
    (void)in_sizes; (void)n_in; (void)out_size;

    cudaFuncSetAttribute(proj_kernel, cudaFuncAttributeMaxDynamicSharedMemorySize, GSMEM);
    cudaFuncSetAttribute(pv_kernel,   cudaFuncAttributeMaxDynamicSharedMemorySize, WSMEM);
    cudaFuncSetAttribute(out_kernel,  cudaFuncAttributeMaxDynamicSharedMemorySize, WSMEM);
    cudaFuncSetAttribute(s_softmax_kernel, cudaFuncAttributeMaxDynamicSharedMemorySize, S_SMEM);

    // K0: merged weight transpose/convert + x -> bf16
    prepxbf_kernel<<<XBF_BLOCKS + PREP_BLOCKS, 256>>>(x, w_theta, w_phi, w_g, w_o);
    // K1: projections
    proj_kernel<<<dim3(NPROJ / 128, M_TOT / 128), 256, GSMEM>>>();
    // K2: merged pooling (phi row-major + g transposed)
    pool_kernel<<<POOLPHI_BLOCKS + POOLVT_BLOCKS, 256>>>();
    // K3: S + softmax -> P
    s_softmax_kernel<<<dim3(HW / 16, 8), 256, S_SMEM>>>();
    // K4: P @ V  (128x256 tile, P read once)
    pv_kernel<<<dim3(HW / 128, 8), 512, WSMEM>>>();
    // K5: output projection + residual (128x256 tile)
    out_kernel<<<dim3(C_IN / 256, M_TOT / 128), 512, WSMEM>>>(x, gamma, out);
}